// round 2
// baseline (speedup 1.0000x reference)
#include <cuda_runtime.h>

#define BB   4
#define NN   1024
#define DDIM 512
#define HH   8
#define DHH  64
#define LLAY 6
#define DFFN 2048
#define MROWS (BB*NN)
#define NEGINF (-1000000000.0f)

// ---------------- scratch buffers (static device memory; no allocs) ----------------
__device__ float buf_h [MROWS*DDIM];
__device__ float buf_q [MROWS*DDIM];
__device__ float buf_k [MROWS*DDIM];
__device__ float buf_v [MROWS*DDIM];
__device__ float buf_o [MROWS*DDIM];
__device__ float buf_x [MROWS*DDIM];
__device__ float buf_ff[MROWS*DFFN];

// ---------------- LayerNorm: one block per row, 256 threads, D=512 ----------------
__global__ __launch_bounds__(256) void ln_kernel(const float* __restrict__ X,
                                                 const float* __restrict__ gam,
                                                 const float* __restrict__ bet,
                                                 float* __restrict__ Y)
{
    int row = blockIdx.x;
    const float* x = X + (size_t)row * DDIM;
    int tid = threadIdx.x;
    float v0 = x[tid], v1 = x[tid + 256];

    __shared__ float red[8];
    __shared__ float stat[2];

    float s = v0 + v1;
    #pragma unroll
    for (int off = 16; off; off >>= 1) s += __shfl_xor_sync(0xffffffffu, s, off);
    if ((tid & 31) == 0) red[tid >> 5] = s;
    __syncthreads();
    if (tid < 8) {
        float t = red[tid];
        #pragma unroll
        for (int off = 4; off; off >>= 1) t += __shfl_xor_sync(0xffu, t, off);
        if (tid == 0) stat[0] = t * (1.0f / DDIM);
    }
    __syncthreads();
    float mean = stat[0];
    float d0 = v0 - mean, d1 = v1 - mean;
    float q = d0*d0 + d1*d1;
    #pragma unroll
    for (int off = 16; off; off >>= 1) q += __shfl_xor_sync(0xffffffffu, q, off);
    if ((tid & 31) == 0) red[tid >> 5] = q;
    __syncthreads();
    if (tid < 8) {
        float t = red[tid];
        #pragma unroll
        for (int off = 4; off; off >>= 1) t += __shfl_xor_sync(0xffu, t, off);
        if (tid == 0) stat[1] = rsqrtf(t * (1.0f / DDIM) + 1e-5f);
    }
    __syncthreads();
    float rs = stat[1];
    Y[(size_t)row*DDIM + tid]       = d0 * rs * gam[tid]       + bet[tid];
    Y[(size_t)row*DDIM + tid + 256] = d1 * rs * gam[tid + 256] + bet[tid + 256];
}

// ---------------- GEMM: C[M,Nc] = A[M,K] @ W[K,Nc] (+bias, +gelu, +residual) -------
// BM=128, BN=64, BK=16, 256 threads, 8x4 per-thread microtile.
#define GBM 128
#define GBN 64
#define GBK 16

__device__ __forceinline__ float gelu_exact(float x) {
    return 0.5f * x * (1.0f + erff(x * 0.70710678118654752440f));
}

__global__ __launch_bounds__(256) void gemm_kernel(const float* __restrict__ A,
                                                   const float* __restrict__ W,
                                                   const float* __restrict__ bias,
                                                   const float* __restrict__ resid,
                                                   float* __restrict__ C,
                                                   int M, int K, int Nc, int act)
{
    __shared__ float As[GBK][GBM + 4];   // stride 132: float4-aligned rows
    __shared__ float Ws[GBK][GBN];

    int tid = threadIdx.x;
    int block_row = blockIdx.y * GBM;
    int block_col = blockIdx.x * GBN;
    int ty = tid >> 4;   // 0..15
    int tx = tid & 15;   // 0..15

    float acc[8][4];
    #pragma unroll
    for (int i = 0; i < 8; i++)
        #pragma unroll
        for (int j = 0; j < 4; j++) acc[i][j] = 0.f;

    for (int k0 = 0; k0 < K; k0 += GBK) {
        // A tile: 128x16 as float4, transposed into shared
        #pragma unroll
        for (int it = 0; it < 2; it++) {
            int linear = tid + it * 256;      // 0..511
            int k4  = linear & 3;
            int row = linear >> 2;            // 0..127
            float4 v = *reinterpret_cast<const float4*>(
                &A[(size_t)(block_row + row) * K + k0 + k4 * 4]);
            As[k4*4+0][row] = v.x;
            As[k4*4+1][row] = v.y;
            As[k4*4+2][row] = v.z;
            As[k4*4+3][row] = v.w;
        }
        // W tile: 16x64 as float4
        {
            int col4 = tid & 15;
            int krow = tid >> 4;
            float4 v = *reinterpret_cast<const float4*>(
                &W[(size_t)(k0 + krow) * Nc + block_col + col4 * 4]);
            *reinterpret_cast<float4*>(&Ws[krow][col4 * 4]) = v;
        }
        __syncthreads();

        #pragma unroll
        for (int kk = 0; kk < GBK; kk++) {
            float4 a0 = *reinterpret_cast<const float4*>(&As[kk][ty * 8]);
            float4 a1 = *reinterpret_cast<const float4*>(&As[kk][ty * 8 + 4]);
            float4 wv = *reinterpret_cast<const float4*>(&Ws[kk][tx * 4]);
            float a[8] = {a0.x, a0.y, a0.z, a0.w, a1.x, a1.y, a1.z, a1.w};
            float wreg[4] = {wv.x, wv.y, wv.z, wv.w};
            #pragma unroll
            for (int i = 0; i < 8; i++)
                #pragma unroll
                for (int j = 0; j < 4; j++)
                    acc[i][j] += a[i] * wreg[j];
        }
        __syncthreads();
    }

    // epilogue: float4 stores
    #pragma unroll
    for (int i = 0; i < 8; i++) {
        int row = block_row + ty * 8 + i;
        int col = block_col + tx * 4;
        float4 c = make_float4(acc[i][0], acc[i][1], acc[i][2], acc[i][3]);
        if (bias) {
            float4 bb = *reinterpret_cast<const float4*>(&bias[col]);
            c.x += bb.x; c.y += bb.y; c.z += bb.z; c.w += bb.w;
        }
        if (act) {
            c.x = gelu_exact(c.x); c.y = gelu_exact(c.y);
            c.z = gelu_exact(c.z); c.w = gelu_exact(c.w);
        }
        if (resid) {
            float4 rr = *reinterpret_cast<const float4*>(&resid[(size_t)row * Nc + col]);
            c.x += rr.x; c.y += rr.y; c.z += rr.z; c.w += rr.w;
        }
        *reinterpret_cast<float4*>(&C[(size_t)row * Nc + col]) = c;
    }
}

// ---------------- Attention: flash-style, fused bias mask ----------------
// Block = (b, h, 64-query tile). 256 threads = 8 warps, 8 query rows per warp.
// Key tiles of 32; lane owns one key within the tile.
#define TQ 64
#define TK 32

__global__ __launch_bounds__(256) void attn_kernel(const float* __restrict__ Q,
                                                   const float* __restrict__ Kg,
                                                   const float* __restrict__ Vg,
                                                   const float* __restrict__ xy,
                                                   const int* __restrict__ alive,
                                                   const int* __restrict__ species,
                                                   float* __restrict__ O)
{
    int b = blockIdx.z, h = blockIdx.y;
    int q0 = blockIdx.x * TQ;
    int tid = threadIdx.x;
    int w = tid >> 5, lane = tid & 31;

    __shared__ float Qs[TQ][DHH];      // broadcast reads
    __shared__ float Ks[TK][DHH + 1];  // Ks[lane][d]: bank = (lane+d)%32 -> conflict-free
    __shared__ float Vs[TK][DHH];      // Vs[j][lane(+32)]: conflict-free
    __shared__ float Wp[8][8][TK];
    __shared__ float xs[TQ], ys[TQ];
    __shared__ int   sps[TQ];

    // load Q tile + per-query attributes
    for (int i = tid; i < TQ * DHH; i += 256) {
        int r = i >> 6, d = i & 63;
        Qs[r][d] = Q[((size_t)(b * NN + q0 + r) * DDIM) + h * DHH + d];
    }
    if (tid < TQ) {
        int qg = q0 + tid;
        xs[tid]  = xy[(b * NN + qg) * 2];
        ys[tid]  = xy[(b * NN + qg) * 2 + 1];
        sps[tid] = species[b * NN + qg];
    }
    __syncthreads();

    float m[8], lsum[8], o0[8], o1[8];
    #pragma unroll
    for (int r = 0; r < 8; r++) { m[r] = -3.0e38f; lsum[r] = 0.f; o0[r] = 0.f; o1[r] = 0.f; }

    for (int jt = 0; jt < NN; jt += TK) {
        // load K/V tiles cooperatively
        for (int i = tid; i < TK * DHH; i += 256) {
            int j = i >> 6, d = i & 63;
            size_t base = ((size_t)(b * NN + jt + j) * DDIM) + h * DHH + d;
            Ks[j][d] = Kg[base];
            Vs[j][d] = Vg[base];
        }
        __syncthreads();

        // per-lane key attributes
        int jg = jt + lane;
        float xj = xy[(b * NN + jg) * 2];
        float yj = xy[(b * NN + jg) * 2 + 1];
        float bias_alive = (alive[b * NN + jg] == 0) ? NEGINF : 0.f;
        int spj = species[b * NN + jg];
        bool ja = (spj < 2), jp = (spj == 2);

        // scores: 8 rows per warp, lane = key index
        float s[8];
        #pragma unroll
        for (int r = 0; r < 8; r++) s[r] = 0.f;
        #pragma unroll 16
        for (int d = 0; d < DHH; d++) {
            float kv = Ks[lane][d];
            #pragma unroll
            for (int r = 0; r < 8; r++) s[r] += Qs[w * 8 + r][d] * kv;
        }

        #pragma unroll
        for (int r = 0; r < 8; r++) {
            int qr = w * 8 + r;
            // bias (exact, no FMA contraction on the boundary compare)
            float dx = __fadd_rn(xs[qr], -xj);
            float dy = __fadd_rn(ys[qr], -yj);
            float d2 = __fadd_rn(__fmul_rn(dx, dx), __fmul_rn(dy, dy));
            float bias = bias_alive;
            if (d2 > 100.0f) bias += NEGINF;
            int spi = sps[qr];
            bool ia = (spi < 2), ip = (spi == 2);
            if ((ia && jp) || (ip && ja)) bias += NEGINF;

            float sv = s[r] * 0.125f + bias;

            float mx = sv;
            #pragma unroll
            for (int off = 16; off; off >>= 1) mx = fmaxf(mx, __shfl_xor_sync(0xffffffffu, mx, off));
            float newm = fmaxf(m[r], mx);
            float corr = expf(m[r] - newm);
            float p = expf(sv - newm);
            float ps = p;
            #pragma unroll
            for (int off = 16; off; off >>= 1) ps += __shfl_xor_sync(0xffffffffu, ps, off);
            lsum[r] = lsum[r] * corr + ps;
            o0[r] *= corr;
            o1[r] *= corr;
            m[r] = newm;
            Wp[w][r][lane] = p;
        }
        __syncwarp();

        // O accumulation: lane owns dims (lane, lane+32)
        #pragma unroll 8
        for (int j = 0; j < TK; j++) {
            float v0 = Vs[j][lane];
            float v1 = Vs[j][lane + 32];
            #pragma unroll
            for (int r = 0; r < 8; r++) {
                float wv = Wp[w][r][j];
                o0[r] += wv * v0;
                o1[r] += wv * v1;
            }
        }
        __syncthreads();
    }

    #pragma unroll
    for (int r = 0; r < 8; r++) {
        int qg = q0 + w * 8 + r;
        float inv = 1.0f / lsum[r];
        size_t base = ((size_t)(b * NN + qg) * DDIM) + h * DHH;
        O[base + lane]      = o0[r] * inv;
        O[base + 32 + lane] = o1[r] * inv;
    }
}

// ---------------- host orchestration ----------------
extern "C" void kernel_launch(void* const* d_in, const int* in_sizes, int n_in,
                              void* d_out, int out_size)
{
    (void)in_sizes; (void)n_in; (void)out_size;
    const float* tokens  = (const float*)d_in[0];
    const float* xy      = (const float*)d_in[1];
    const float* Wq      = (const float*)d_in[2];
    const float* Wk      = (const float*)d_in[3];
    const float* Wv      = (const float*)d_in[4];
    const float* Wo      = (const float*)d_in[5];
    const float* bo      = (const float*)d_in[6];
    const float* W1      = (const float*)d_in[7];
    const float* b1      = (const float*)d_in[8];
    const float* W2      = (const float*)d_in[9];
    const float* b2      = (const float*)d_in[10];
    const float* g1      = (const float*)d_in[11];
    const float* be1     = (const float*)d_in[12];
    const float* g2      = (const float*)d_in[13];
    const float* be2     = (const float*)d_in[14];
    const float* gf      = (const float*)d_in[15];
    const float* bf      = (const float*)d_in[16];
    const int*   alive   = (const int*)d_in[17];
    const int*   species = (const int*)d_in[18];

    float *p_h, *p_q, *p_k, *p_v, *p_o, *p_x, *p_ff;
    cudaGetSymbolAddress((void**)&p_h,  buf_h);
    cudaGetSymbolAddress((void**)&p_q,  buf_q);
    cudaGetSymbolAddress((void**)&p_k,  buf_k);
    cudaGetSymbolAddress((void**)&p_v,  buf_v);
    cudaGetSymbolAddress((void**)&p_o,  buf_o);
    cudaGetSymbolAddress((void**)&p_x,  buf_x);
    cudaGetSymbolAddress((void**)&p_ff, buf_ff);

    const int M = MROWS;
    dim3 gemmD(DDIM / GBN, M / GBM);     // (8, 32)
    dim3 gemmF(DFFN / GBN, M / GBM);     // (32, 32)
    dim3 attnG(NN / TQ, HH, BB);         // (16, 8, 4)

    for (int l = 0; l < LLAY; l++) {
        const float* xsrc = (l == 0) ? tokens : p_x;
        const float* Wq_l = Wq + (size_t)l * DDIM * DDIM;
        const float* Wk_l = Wk + (size_t)l * DDIM * DDIM;
        const float* Wv_l = Wv + (size_t)l * DDIM * DDIM;
        const float* Wo_l = Wo + (size_t)l * DDIM * DDIM;
        const float* W1_l = W1 + (size_t)l * DDIM * DFFN;
        const float* W2_l = W2 + (size_t)l * DFFN * DDIM;

        ln_kernel<<<M, 256>>>(xsrc, g1 + l * DDIM, be1 + l * DDIM, p_h);

        gemm_kernel<<<gemmD, 256>>>(p_h, Wq_l, nullptr, nullptr, p_q, M, DDIM, DDIM, 0);
        gemm_kernel<<<gemmD, 256>>>(p_h, Wk_l, nullptr, nullptr, p_k, M, DDIM, DDIM, 0);
        gemm_kernel<<<gemmD, 256>>>(p_h, Wv_l, nullptr, nullptr, p_v, M, DDIM, DDIM, 0);

        attn_kernel<<<attnG, 256>>>(p_q, p_k, p_v, xy, alive, species, p_o);

        gemm_kernel<<<gemmD, 256>>>(p_o, Wo_l, bo + l * DDIM, xsrc, p_x, M, DDIM, DDIM, 0);

        ln_kernel<<<M, 256>>>(p_x, g2 + l * DDIM, be2 + l * DDIM, p_h);

        gemm_kernel<<<gemmF, 256>>>(p_h, W1_l, b1 + l * DFFN, nullptr, p_ff, M, DDIM, DFFN, 1);
        gemm_kernel<<<gemmD, 256>>>(p_ff, W2_l, b2 + l * DDIM, p_x, p_x, M, DFFN, DDIM, 0);
    }

    ln_kernel<<<M, 256>>>(p_x, gf, bf, (float*)d_out);
}

// round 4
// speedup vs baseline: 1.0728x; 1.0728x over previous
#include <cuda_runtime.h>
#include <mma.h>
using namespace nvcuda;

#define BB   4
#define NN   1024
#define DDIM 512
#define HH   8
#define DHH  64
#define LLAY 6
#define DFFN 2048
#define MROWS (BB*NN)
#define NEGINF (-1000000000.0f)

// ---------------- scratch (static device memory; no allocs) ----------------
__device__ float buf_h [MROWS*DDIM];
__device__ float buf_q [MROWS*DDIM];
__device__ float buf_k [MROWS*DDIM];
__device__ float buf_v [MROWS*DDIM];
__device__ float buf_o [MROWS*DDIM];
__device__ float buf_x [MROWS*DDIM];
__device__ float buf_ff[MROWS*DFFN];
__device__ unsigned buf_mask[(size_t)BB*NN*(NN/32)];   // 1 = unmasked pair

// ---------------- LayerNorm ----------------
__global__ __launch_bounds__(256) void ln_kernel(const float* __restrict__ X,
                                                 const float* __restrict__ gam,
                                                 const float* __restrict__ bet,
                                                 float* __restrict__ Y)
{
    int row = blockIdx.x;
    const float* x = X + (size_t)row * DDIM;
    int tid = threadIdx.x;
    float v0 = x[tid], v1 = x[tid + 256];

    __shared__ float red[8];
    __shared__ float stat[2];

    float s = v0 + v1;
    #pragma unroll
    for (int off = 16; off; off >>= 1) s += __shfl_xor_sync(0xffffffffu, s, off);
    if ((tid & 31) == 0) red[tid >> 5] = s;
    __syncthreads();
    if (tid < 8) {
        float t = red[tid];
        #pragma unroll
        for (int off = 4; off; off >>= 1) t += __shfl_xor_sync(0xffu, t, off);
        if (tid == 0) stat[0] = t * (1.0f / DDIM);
    }
    __syncthreads();
    float mean = stat[0];
    float d0 = v0 - mean, d1 = v1 - mean;
    float q = d0*d0 + d1*d1;
    #pragma unroll
    for (int off = 16; off; off >>= 1) q += __shfl_xor_sync(0xffffffffu, q, off);
    if ((tid & 31) == 0) red[tid >> 5] = q;
    __syncthreads();
    if (tid < 8) {
        float t = red[tid];
        #pragma unroll
        for (int off = 4; off; off >>= 1) t += __shfl_xor_sync(0xffu, t, off);
        if (tid == 0) stat[1] = rsqrtf(t * (1.0f / DDIM) + 1e-5f);
    }
    __syncthreads();
    float rs = stat[1];
    Y[(size_t)row*DDIM + tid]       = d0 * rs * gam[tid]       + bet[tid];
    Y[(size_t)row*DDIM + tid + 256] = d1 * rs * gam[tid + 256] + bet[tid + 256];
}

// ---------------- mask precompute: bit=1 means pair (q,k) is unmasked ----------------
__global__ __launch_bounds__(256) void mask_kernel(const float* __restrict__ xy,
                                                   const int* __restrict__ alive,
                                                   const int* __restrict__ species,
                                                   unsigned* __restrict__ maskw)
{
    int b = blockIdx.y;
    int q = blockIdx.x;
    int tid = threadIdx.x;
    float xq = xy[(b*NN+q)*2], yq = xy[(b*NN+q)*2+1];
    int sq = species[b*NN+q];
    bool qa = sq < 2, qp = sq == 2;
    for (int k0 = 0; k0 < NN; k0 += 256) {
        int k = k0 + tid;
        float xk = xy[(b*NN+k)*2], yk = xy[(b*NN+k)*2+1];
        bool un = alive[b*NN+k] != 0;
        float dx = __fadd_rn(xq, -xk), dy = __fadd_rn(yq, -yk);
        float d2 = __fadd_rn(__fmul_rn(dx,dx), __fmul_rn(dy,dy));
        if (d2 > 100.0f) un = false;
        int sk = species[b*NN+k];
        bool ka = sk < 2, kp = sk == 2;
        if ((qa && kp) || (qp && ka)) un = false;
        unsigned bal = __ballot_sync(0xffffffffu, un);
        if ((tid & 31) == 0) maskw[((size_t)(b*NN+q))*(NN/32) + (k >> 5)] = bal;
    }
}

// ---------------- tf32 tensor-core GEMM ----------------
// BM=128, BK=32, BNT in {64,128}. 8 warps: 4 (M) x 2 (N); warp tile 32 x BNT/2.
#define GBM 128
#define GBK 32
#define GLDA 40

__device__ __forceinline__ float gelu_exact(float x) {
    return 0.5f * x * (1.0f + erff(x * 0.70710678118654752440f));
}

template<int BNT>
__global__ __launch_bounds__(256) void gemm_tc(const float* __restrict__ A,
                                               const float* __restrict__ W,
                                               const float* __restrict__ bias,
                                               const float* __restrict__ resid,
                                               float* __restrict__ C,
                                               int M, int K, int Nc, int act)
{
    constexpr int NF  = BNT / 32;        // n-frags per warp (2 or 4)
    constexpr int LDB = BNT + 8;
    __shared__ alignas(16) float As[GBM * GLDA];
    __shared__ alignas(16) float Bs[GBK * LDB];
    __shared__ float stage[8 * 256];

    int tid  = threadIdx.x;
    int warp = tid >> 5;
    int lane = tid & 31;
    int row0 = blockIdx.y * GBM;
    int col0 = blockIdx.x * BNT;
    int wm = warp >> 1;          // 0..3
    int wn = warp & 1;           // 0..1

    wmma::fragment<wmma::accumulator, 16,16,8, float> acc[2][NF];
    #pragma unroll
    for (int mi = 0; mi < 2; mi++)
        #pragma unroll
        for (int ni = 0; ni < NF; ni++) wmma::fill_fragment(acc[mi][ni], 0.f);

    for (int k0 = 0; k0 < K; k0 += GBK) {
        // A tile 128 x 32 (float4)
        #pragma unroll
        for (int it = 0; it < 4; it++) {
            int f  = it * 256 + tid;          // 1024 float4s
            int r  = f >> 3;
            int c4 = (f & 7) * 4;
            float4 v = *reinterpret_cast<const float4*>(&A[(size_t)(row0 + r) * K + k0 + c4]);
            *reinterpret_cast<float4*>(&As[r * GLDA + c4]) = v;
        }
        // B tile 32 x BNT (float4)
        #pragma unroll
        for (int it = 0; it < GBK * BNT / 4 / 256; it++) {
            int f  = it * 256 + tid;
            int r  = f / (BNT / 4);
            int c4 = (f % (BNT / 4)) * 4;
            float4 v = *reinterpret_cast<const float4*>(&W[(size_t)(k0 + r) * Nc + col0 + c4]);
            *reinterpret_cast<float4*>(&Bs[r * LDB + c4]) = v;
        }
        __syncthreads();

        #pragma unroll
        for (int kk = 0; kk < GBK; kk += 8) {
            wmma::fragment<wmma::matrix_a, 16,16,8, wmma::precision::tf32, wmma::row_major> af[2];
            wmma::fragment<wmma::matrix_b, 16,16,8, wmma::precision::tf32, wmma::row_major> bf[NF];
            #pragma unroll
            for (int mi = 0; mi < 2; mi++) {
                wmma::load_matrix_sync(af[mi], &As[(wm*32 + mi*16) * GLDA + kk], GLDA);
                #pragma unroll
                for (int t = 0; t < af[mi].num_elements; t++)
                    af[mi].x[t] = wmma::__float_to_tf32(af[mi].x[t]);
            }
            #pragma unroll
            for (int ni = 0; ni < NF; ni++) {
                wmma::load_matrix_sync(bf[ni], &Bs[kk * LDB + wn*(16*NF) + ni*16], LDB);
                #pragma unroll
                for (int t = 0; t < bf[ni].num_elements; t++)
                    bf[ni].x[t] = wmma::__float_to_tf32(bf[ni].x[t]);
            }
            #pragma unroll
            for (int mi = 0; mi < 2; mi++)
                #pragma unroll
                for (int ni = 0; ni < NF; ni++)
                    wmma::mma_sync(acc[mi][ni], af[mi], bf[ni], acc[mi][ni]);
        }
        __syncthreads();
    }

    // epilogue through per-warp staging tile
    float* st = &stage[warp * 256];
    #pragma unroll
    for (int mi = 0; mi < 2; mi++) {
        #pragma unroll
        for (int ni = 0; ni < NF; ni++) {
            wmma::store_matrix_sync(st, acc[mi][ni], 16, wmma::mem_row_major);
            __syncwarp();
            int gr0 = row0 + wm*32 + mi*16;
            int gc0 = col0 + wn*(16*NF) + ni*16;
            #pragma unroll
            for (int i = 0; i < 8; i++) {
                int idx = i*32 + lane;
                int r = idx >> 4, c = idx & 15;
                float v = st[idx];
                if (bias)  v += bias[gc0 + c];
                if (act)   v  = gelu_exact(v);
                if (resid) v += resid[(size_t)(gr0 + r) * Nc + gc0 + c];
                C[(size_t)(gr0 + r) * Nc + gc0 + c] = v;
            }
            __syncwarp();
        }
    }
}

// ---------------- attention: flash-style, precomputed bitmask, sparse exp ----------------
#define TQ 64
#define TK 32
#define KLD (DHH + 4)   // 68
#define VLD (TK + 4)    // 36

__global__ __launch_bounds__(256) void attn_kernel(const float* __restrict__ Q,
                                                   const float* __restrict__ Kg,
                                                   const float* __restrict__ Vg,
                                                   const unsigned* __restrict__ maskw,
                                                   const float* __restrict__ xy,
                                                   const int* __restrict__ alive,
                                                   const int* __restrict__ species,
                                                   float* __restrict__ O)
{
    int b = blockIdx.z, h = blockIdx.y;
    int q0 = blockIdx.x * TQ;
    int tid = threadIdx.x;
    int w = tid >> 5, lane = tid & 31;

    __shared__ alignas(16) float Qs[TQ][DHH];
    __shared__ alignas(16) float Ks[TK][KLD];
    __shared__ alignas(16) float Vt[DHH][VLD];   // Vt[d][j] = V[j][d]
    __shared__ alignas(16) float Wp[8][8][TK];
    __shared__ int badflag;

    if (tid == 0) badflag = 0;

    // Q tile (float4)
    for (int i = tid; i < TQ * DHH / 4; i += 256) {
        int r = i >> 4;
        int d4 = (i & 15) * 4;
        float4 qv = *reinterpret_cast<const float4*>(&Q[((size_t)(b*NN + q0 + r) * DDIM) + h*DHH + d4]);
        *reinterpret_cast<float4*>(&Qs[r][d4]) = qv;
    }
    __syncthreads();

    float m[8], lsum[8], o0[8], o1[8];
    #pragma unroll
    for (int r = 0; r < 8; r++) { m[r] = -3.0e38f; lsum[r] = 0.f; o0[r] = 0.f; o1[r] = 0.f; }

    const size_t mrow = (size_t)(b * NN) * (NN / 32);

    for (int jt = 0; jt < NN; jt += TK) {
        // K/V tiles (float4 global; V transposed into Vt)
        for (int i = tid; i < TK * DHH / 4; i += 256) {
            int j = i >> 4;
            int d4 = (i & 15) * 4;
            size_t base = ((size_t)(b*NN + jt + j) * DDIM) + h*DHH + d4;
            float4 kv = *reinterpret_cast<const float4*>(&Kg[base]);
            *reinterpret_cast<float4*>(&Ks[j][d4]) = kv;
            float4 vv = *reinterpret_cast<const float4*>(&Vg[base]);
            Vt[d4+0][j] = vv.x; Vt[d4+1][j] = vv.y; Vt[d4+2][j] = vv.z; Vt[d4+3][j] = vv.w;
        }
        __syncthreads();

        unsigned um[8]; unsigned any = 0;
        #pragma unroll
        for (int r = 0; r < 8; r++) {
            um[r] = maskw[mrow + (size_t)(q0 + w*8 + r) * (NN/32) + (jt >> 5)];
            any |= um[r];
        }

        if (any) {
            // scores for 8 rows, lane = key
            float s[8];
            #pragma unroll
            for (int r = 0; r < 8; r++) s[r] = 0.f;
            #pragma unroll 4
            for (int d = 0; d < DHH; d += 4) {
                float4 kv = *reinterpret_cast<const float4*>(&Ks[lane][d]);
                #pragma unroll
                for (int r = 0; r < 8; r++) {
                    float4 qv = *reinterpret_cast<const float4*>(&Qs[w*8 + r][d]);
                    s[r] += qv.x*kv.x + qv.y*kv.y + qv.z*kv.z + qv.w*kv.w;
                }
            }

            #pragma unroll
            for (int r = 0; r < 8; r++) {
                if (um[r] == 0) {             // warp-uniform
                    Wp[w][r][lane] = 0.f;
                    continue;
                }
                bool un = (um[r] >> lane) & 1u;
                float sv = un ? s[r] * 0.125f : -3.0e38f;
                float mx = sv;
                #pragma unroll
                for (int off = 16; off; off >>= 1) mx = fmaxf(mx, __shfl_xor_sync(0xffffffffu, mx, off));
                float newm = fmaxf(m[r], mx);
                float corr = 1.f;
                if (newm > m[r]) corr = expf(m[r] - newm);   // uniform branch
                float p = expf(sv - newm);                    // masked lanes underflow to 0 exactly
                float ps = p;
                #pragma unroll
                for (int off = 16; off; off >>= 1) ps += __shfl_xor_sync(0xffffffffu, ps, off);
                lsum[r] = lsum[r] * corr + ps;
                o0[r] *= corr; o1[r] *= corr;
                m[r] = newm;
                Wp[w][r][lane] = p;
            }
            __syncwarp();

            // O accumulation: lane owns dims (lane, lane+32)
            #pragma unroll 4
            for (int j = 0; j < TK; j += 4) {
                float4 va = *reinterpret_cast<const float4*>(&Vt[lane][j]);
                float4 vb = *reinterpret_cast<const float4*>(&Vt[lane + 32][j]);
                #pragma unroll
                for (int r = 0; r < 8; r++) {
                    float4 wv = *reinterpret_cast<const float4*>(&Wp[w][r][j]);
                    o0[r] += wv.x*va.x + wv.y*va.y + wv.z*va.z + wv.w*va.w;
                    o1[r] += wv.x*vb.x + wv.y*vb.y + wv.z*vb.z + wv.w*vb.w;
                }
            }
        }
        __syncthreads();
    }

    // rare path: rows where every key is masked -> exact biased softmax
    bool bad[8]; bool anyb = false;
    #pragma unroll
    for (int r = 0; r < 8; r++) { bad[r] = (lsum[r] == 0.f); anyb |= bad[r]; }
    if (lane == 0 && anyb) atomicExch(&badflag, 1);
    __syncthreads();

    if (badflag) {
        for (int jt = 0; jt < NN; jt += TK) {
            for (int i = tid; i < TK * DHH / 4; i += 256) {
                int j = i >> 4;
                int d4 = (i & 15) * 4;
                size_t base = ((size_t)(b*NN + jt + j) * DDIM) + h*DHH + d4;
                float4 kv = *reinterpret_cast<const float4*>(&Kg[base]);
                *reinterpret_cast<float4*>(&Ks[j][d4]) = kv;
                float4 vv = *reinterpret_cast<const float4*>(&Vg[base]);
                Vt[d4+0][j] = vv.x; Vt[d4+1][j] = vv.y; Vt[d4+2][j] = vv.z; Vt[d4+3][j] = vv.w;
            }
            __syncthreads();

            int jg = jt + lane;
            float xj = xy[(b*NN + jg)*2], yj = xy[(b*NN + jg)*2 + 1];
            float biasA = (alive[b*NN + jg] == 0) ? NEGINF : 0.f;
            int spj = species[b*NN + jg];
            bool ja = (spj < 2), jp = (spj == 2);

            float s[8];
            #pragma unroll
            for (int r = 0; r < 8; r++) s[r] = 0.f;
            #pragma unroll 4
            for (int d = 0; d < DHH; d += 4) {
                float4 kv = *reinterpret_cast<const float4*>(&Ks[lane][d]);
                #pragma unroll
                for (int r = 0; r < 8; r++) {
                    float4 qv = *reinterpret_cast<const float4*>(&Qs[w*8 + r][d]);
                    s[r] += qv.x*kv.x + qv.y*kv.y + qv.z*kv.z + qv.w*kv.w;
                }
            }

            #pragma unroll
            for (int r = 0; r < 8; r++) {
                if (!bad[r]) { Wp[w][r][lane] = 0.f; continue; }
                int qg = q0 + w*8 + r;
                float xq = xy[(b*NN + qg)*2], yq = xy[(b*NN + qg)*2 + 1];
                int sq = species[b*NN + qg];
                bool ia = (sq < 2), ip = (sq == 2);
                float dx = __fadd_rn(xq, -xj), dy = __fadd_rn(yq, -yj);
                float d2 = __fadd_rn(__fmul_rn(dx,dx), __fmul_rn(dy,dy));
                float biasv = biasA;
                if (d2 > 100.0f) biasv += NEGINF;
                if ((ia && jp) || (ip && ja)) biasv += NEGINF;
                float sv = s[r] * 0.125f + biasv;
                float mx = sv;
                #pragma unroll
                for (int off = 16; off; off >>= 1) mx = fmaxf(mx, __shfl_xor_sync(0xffffffffu, mx, off));
                float newm = fmaxf(m[r], mx);
                float corr = expf(m[r] - newm);
                float p = expf(sv - newm);
                float ps = p;
                #pragma unroll
                for (int off = 16; off; off >>= 1) ps += __shfl_xor_sync(0xffffffffu, ps, off);
                lsum[r] = lsum[r] * corr + ps;
                o0[r] *= corr; o1[r] *= corr;
                m[r] = newm;
                Wp[w][r][lane] = p;
            }
            __syncwarp();

            #pragma unroll 4
            for (int j = 0; j < TK; j += 4) {
                float4 va = *reinterpret_cast<const float4*>(&Vt[lane][j]);
                float4 vb = *reinterpret_cast<const float4*>(&Vt[lane + 32][j]);
                #pragma unroll
                for (int r = 0; r < 8; r++) {
                    float4 wv = *reinterpret_cast<const float4*>(&Wp[w][r][j]);
                    o0[r] += wv.x*va.x + wv.y*va.y + wv.z*va.z + wv.w*va.w;
                    o1[r] += wv.x*vb.x + wv.y*vb.y + wv.z*vb.z + wv.w*vb.w;
                }
            }
            __syncthreads();
        }
    }

    #pragma unroll
    for (int r = 0; r < 8; r++) {
        int qg = q0 + w*8 + r;
        float inv = 1.0f / lsum[r];
        size_t base = ((size_t)(b*NN + qg) * DDIM) + h*DHH;
        O[base + lane]      = o0[r] * inv;
        O[base + 32 + lane] = o1[r] * inv;
    }
}

// ---------------- host orchestration ----------------
extern "C" void kernel_launch(void* const* d_in, const int* in_sizes, int n_in,
                              void* d_out, int out_size)
{
    (void)in_sizes; (void)n_in; (void)out_size;
    const float* tokens  = (const float*)d_in[0];
    const float* xy      = (const float*)d_in[1];
    const float* Wq      = (const float*)d_in[2];
    const float* Wk      = (const float*)d_in[3];
    const float* Wv      = (const float*)d_in[4];
    const float* Wo      = (const float*)d_in[5];
    const float* bo      = (const float*)d_in[6];
    const float* W1      = (const float*)d_in[7];
    const float* b1      = (const float*)d_in[8];
    const float* W2      = (const float*)d_in[9];
    const float* b2      = (const float*)d_in[10];
    const float* g1      = (const float*)d_in[11];
    const float* be1     = (const float*)d_in[12];
    const float* g2      = (const float*)d_in[13];
    const float* be2     = (const float*)d_in[14];
    const float* gf      = (const float*)d_in[15];
    const float* bf      = (const float*)d_in[16];
    const int*   alive   = (const int*)d_in[17];
    const int*   species = (const int*)d_in[18];

    float *p_h, *p_q, *p_k, *p_v, *p_o, *p_x, *p_ff;
    unsigned* p_mask;
    cudaGetSymbolAddress((void**)&p_h,  buf_h);
    cudaGetSymbolAddress((void**)&p_q,  buf_q);
    cudaGetSymbolAddress((void**)&p_k,  buf_k);
    cudaGetSymbolAddress((void**)&p_v,  buf_v);
    cudaGetSymbolAddress((void**)&p_o,  buf_o);
    cudaGetSymbolAddress((void**)&p_x,  buf_x);
    cudaGetSymbolAddress((void**)&p_ff, buf_ff);
    cudaGetSymbolAddress((void**)&p_mask, buf_mask);

    const int M = MROWS;
    dim3 gD(DDIM / 64, M / GBM);    // (8, 32)  BNT=64
    dim3 gF(DFFN / 128, M / GBM);   // (16, 32) BNT=128
    dim3 attnG(NN / TQ, HH, BB);    // (16, 8, 4)

    mask_kernel<<<dim3(NN, BB), 256>>>(xy, alive, species, p_mask);

    for (int l = 0; l < LLAY; l++) {
        const float* xsrc = (l == 0) ? tokens : p_x;
        const float* Wq_l = Wq + (size_t)l * DDIM * DDIM;
        const float* Wk_l = Wk + (size_t)l * DDIM * DDIM;
        const float* Wv_l = Wv + (size_t)l * DDIM * DDIM;
        const float* Wo_l = Wo + (size_t)l * DDIM * DDIM;
        const float* W1_l = W1 + (size_t)l * DDIM * DFFN;
        const float* W2_l = W2 + (size_t)l * DFFN * DDIM;

        ln_kernel<<<M, 256>>>(xsrc, g1 + l * DDIM, be1 + l * DDIM, p_h);

        gemm_tc<64><<<gD, 256>>>(p_h, Wq_l, nullptr, nullptr, p_q, M, DDIM, DDIM, 0);
        gemm_tc<64><<<gD, 256>>>(p_h, Wk_l, nullptr, nullptr, p_k, M, DDIM, DDIM, 0);
        gemm_tc<64><<<gD, 256>>>(p_h, Wv_l, nullptr, nullptr, p_v, M, DDIM, DDIM, 0);

        attn_kernel<<<attnG, 256>>>(p_q, p_k, p_v, p_mask, xy, alive, species, p_o);

        gemm_tc<64><<<gD, 256>>>(p_o, Wo_l, bo + l * DDIM, xsrc, p_x, M, DDIM, DDIM, 0);

        ln_kernel<<<M, 256>>>(p_x, g2 + l * DDIM, be2 + l * DDIM, p_h);

        gemm_tc<128><<<gF, 256>>>(p_h, W1_l, b1 + l * DFFN, nullptr, p_ff, M, DDIM, DFFN, 1);
        gemm_tc<64><<<gD, 256>>>(p_ff, W2_l, b2 + l * DDIM, p_x, p_x, M, DFFN, DDIM, 0);
    }

    ln_kernel<<<M, 256>>>(p_x, gf, bf, (float*)d_out);
}